// round 6
// baseline (speedup 1.0000x reference)
#include <cuda_runtime.h>
#include <math.h>
#include <stdint.h>

#define T_TOK 32768
#define D_MOD 1024
#define N_EXP 64
#define CAP   1024
#define SELK  1032
#define CAND  2048

typedef unsigned long long u64;

extern "C" __device__ float __nv_expf(float);
#define EXPF(v) __nv_expf(v)

// Scratch
__device__ float g_logits_t[N_EXP * T_TOK];
__device__ float g_max[N_EXP];
__device__ float g_sum[N_EXP];

// ---------------- f32x2 helpers ----------------
__device__ __forceinline__ u64 pack_dup(float v) {
    u64 d; asm("mov.b64 %0, {%1, %1};" : "=l"(d) : "f"(v)); return d;
}
__device__ __forceinline__ u64 pack2(float lo, float hi) {
    u64 d; asm("mov.b64 %0, {%1, %2};" : "=l"(d) : "f"(lo), "f"(hi)); return d;
}
__device__ __forceinline__ void fma2(u64& d, u64 a, u64 b) {
    asm("fma.rn.f32x2 %0, %1, %2, %0;" : "+l"(d) : "l"(a), "l"(b));
}
__device__ __forceinline__ u64 add2(u64 a, u64 b) {
    u64 d; asm("add.rn.f32x2 %0, %1, %2;" : "=l"(d) : "l"(a), "l"(b)); return d;
}
__device__ __forceinline__ void unpack2(u64 v, float& lo, float& hi) {
    asm("mov.b64 {%0, %1}, %2;" : "=f"(lo), "=f"(hi) : "l"(v));
}
__device__ __forceinline__ void lds_v2u64(uint32_t addr, u64& a, u64& b) {
    asm volatile("ld.shared.v2.u64 {%0, %1}, [%2];"
                 : "=l"(a), "=l"(b) : "r"(addr));
}

// ---------------------------------------------------------------------------
// Kernel 1: SGEMM logits = x @ W + b, split-K2 bit-exact, FFMA2.
// Sequential halves: acc of half-0 spilled (exact) to the logits output
// region at t==31, reloaded in the epilogue, combined (p0+acc1)+bias in RN.
// Block 128 thr, block tile 128m x 64n, thread tile 8m(4 f32x2 pairs) x 8n.
// ---------------------------------------------------------------------------
#define BM   128
#define KT   16
#define ASTR 132

__global__ __launch_bounds__(128, 3) void gemm_kernel(
    const float* __restrict__ x, const float* __restrict__ W,
    const float* __restrict__ bias, float* __restrict__ logits)
{
    __shared__ __align__(16) float As[KT][ASTR];   // [kk][m]
    __shared__ __align__(16) float Bs[KT][N_EXP];  // [kk][n]

    const int tid = threadIdx.x;
    const int tx  = tid & 7;     // n-group (8 experts)
    const int ty  = tid >> 3;    // m-group (8 tokens)
    const int m0  = blockIdx.x * BM;

    const int am  = tid >> 2;    // 0..31
    const int akg = tid & 3;     // k-group of 4
    const int wkk = tid >> 3;    // 0..15
    const int wng = tid & 7;     // n-group of 8

    u64 acc[4][8];
#pragma unroll
    for (int mp = 0; mp < 4; mp++)
#pragma unroll
        for (int n = 0; n < 8; n++) acc[mp][n] = 0ull;

    const uint32_t aBase = (uint32_t)__cvta_generic_to_shared(&As[0][0]);
    const uint32_t aRow  = aBase + (uint32_t)(ty * 8) * 4u;

    float4 xa[4];
#pragma unroll
    for (int p = 0; p < 4; p++)
        xa[p] = *(const float4*)&x[(size_t)(m0 + am + 32 * p) * D_MOD + akg * 4];
    float4 wv0 = *(const float4*)&W[(size_t)wkk * N_EXP + wng * 8];
    float4 wv1 = *(const float4*)&W[(size_t)wkk * N_EXP + wng * 8 + 4];

    for (int t = 0; t < D_MOD / KT; t++) {
#pragma unroll
        for (int p = 0; p < 4; p++) {
            As[akg * 4 + 0][am + 32 * p] = xa[p].x;
            As[akg * 4 + 1][am + 32 * p] = xa[p].y;
            As[akg * 4 + 2][am + 32 * p] = xa[p].z;
            As[akg * 4 + 3][am + 32 * p] = xa[p].w;
        }
        *(float4*)&Bs[wkk][wng * 8]     = wv0;
        *(float4*)&Bs[wkk][wng * 8 + 4] = wv1;
        __syncthreads();

        if (t < D_MOD / KT - 1) {
            const int k0 = (t + 1) * KT;
#pragma unroll
            for (int p = 0; p < 4; p++)
                xa[p] = *(const float4*)&x[(size_t)(m0 + am + 32 * p) * D_MOD + k0 + akg * 4];
            wv0 = *(const float4*)&W[(size_t)(k0 + wkk) * N_EXP + wng * 8];
            wv1 = *(const float4*)&W[(size_t)(k0 + wkk) * N_EXP + wng * 8 + 4];
        }

#pragma unroll
        for (int kk = 0; kk < KT; kk++) {
            u64 a0, a1, a2, a3;
            uint32_t ar = aRow + (uint32_t)(kk * ASTR) * 4u;
            lds_v2u64(ar,      a0, a1);
            lds_v2u64(ar + 16, a2, a3);
            float4 bv0 = *(const float4*)&Bs[kk][tx * 8];
            float4 bv1 = *(const float4*)&Bs[kk][tx * 8 + 4];
            u64 b0 = pack_dup(bv0.x), b1 = pack_dup(bv0.y);
            u64 b2 = pack_dup(bv0.z), b3 = pack_dup(bv0.w);
            u64 b4 = pack_dup(bv1.x), b5 = pack_dup(bv1.y);
            u64 b6 = pack_dup(bv1.z), b7 = pack_dup(bv1.w);
            fma2(acc[0][0], a0, b0); fma2(acc[0][1], a0, b1);
            fma2(acc[0][2], a0, b2); fma2(acc[0][3], a0, b3);
            fma2(acc[0][4], a0, b4); fma2(acc[0][5], a0, b5);
            fma2(acc[0][6], a0, b6); fma2(acc[0][7], a0, b7);
            fma2(acc[1][0], a1, b0); fma2(acc[1][1], a1, b1);
            fma2(acc[1][2], a1, b2); fma2(acc[1][3], a1, b3);
            fma2(acc[1][4], a1, b4); fma2(acc[1][5], a1, b5);
            fma2(acc[1][6], a1, b6); fma2(acc[1][7], a1, b7);
            fma2(acc[2][0], a2, b0); fma2(acc[2][1], a2, b1);
            fma2(acc[2][2], a2, b2); fma2(acc[2][3], a2, b3);
            fma2(acc[2][4], a2, b4); fma2(acc[2][5], a2, b5);
            fma2(acc[2][6], a2, b6); fma2(acc[2][7], a2, b7);
            fma2(acc[3][0], a3, b0); fma2(acc[3][1], a3, b1);
            fma2(acc[3][2], a3, b2); fma2(acc[3][3], a3, b3);
            fma2(acc[3][4], a3, b4); fma2(acc[3][5], a3, b5);
            fma2(acc[3][6], a3, b6); fma2(acc[3][7], a3, b7);
        }
        __syncthreads();

        if (t == 31) {
            // spill half-0 accumulators (exact bit copies) to the logits
            // output region; zero accs for half-1
#pragma unroll
            for (int mp = 0; mp < 4; mp++) {
                float r0[8], r1[8];
#pragma unroll
                for (int n = 0; n < 8; n++) {
                    unpack2(acc[mp][n], r0[n], r1[n]);
                    acc[mp][n] = 0ull;
                }
                const int m_lo = m0 + ty * 8 + mp * 2;
                *(float4*)&logits[(size_t)m_lo * N_EXP + tx * 8] =
                    make_float4(r0[0], r0[1], r0[2], r0[3]);
                *(float4*)&logits[(size_t)m_lo * N_EXP + tx * 8 + 4] =
                    make_float4(r0[4], r0[5], r0[6], r0[7]);
                *(float4*)&logits[(size_t)(m_lo + 1) * N_EXP + tx * 8] =
                    make_float4(r1[0], r1[1], r1[2], r1[3]);
                *(float4*)&logits[(size_t)(m_lo + 1) * N_EXP + tx * 8 + 4] =
                    make_float4(r1[4], r1[5], r1[6], r1[7]);
            }
        }
    }

    // epilogue: reload half-0 partials, combine (p0 + acc1) + bias in RN
    float col[8][8];   // [n][m]
#pragma unroll
    for (int mp = 0; mp < 4; mp++) {
        const int m_lo = m0 + ty * 8 + mp * 2;
        float4 p00 = *(const float4*)&logits[(size_t)m_lo * N_EXP + tx * 8];
        float4 p01 = *(const float4*)&logits[(size_t)m_lo * N_EXP + tx * 8 + 4];
        float4 p10 = *(const float4*)&logits[(size_t)(m_lo + 1) * N_EXP + tx * 8];
        float4 p11 = *(const float4*)&logits[(size_t)(m_lo + 1) * N_EXP + tx * 8 + 4];
        float p0[8] = {p00.x, p00.y, p00.z, p00.w, p01.x, p01.y, p01.z, p01.w};
        float p1[8] = {p10.x, p10.y, p10.z, p10.w, p11.x, p11.y, p11.z, p11.w};
        float r0[8], r1[8];
#pragma unroll
        for (int n = 0; n < 8; n++) {
            u64 s = add2(add2(pack2(p0[n], p1[n]), acc[mp][n]),
                         pack_dup(bias[tx * 8 + n]));
            unpack2(s, r0[n], r1[n]);
            col[n][mp * 2]     = r0[n];
            col[n][mp * 2 + 1] = r1[n];
        }
        *(float4*)&logits[(size_t)m_lo * N_EXP + tx * 8] =
            make_float4(r0[0], r0[1], r0[2], r0[3]);
        *(float4*)&logits[(size_t)m_lo * N_EXP + tx * 8 + 4] =
            make_float4(r0[4], r0[5], r0[6], r0[7]);
        *(float4*)&logits[(size_t)(m_lo + 1) * N_EXP + tx * 8] =
            make_float4(r1[0], r1[1], r1[2], r1[3]);
        *(float4*)&logits[(size_t)(m_lo + 1) * N_EXP + tx * 8 + 4] =
            make_float4(r1[4], r1[5], r1[6], r1[7]);
    }
#pragma unroll
    for (int n = 0; n < 8; n++) {
        float* dst = &g_logits_t[(size_t)(tx * 8 + n) * T_TOK + m0 + ty * 8];
        *(float4*)&dst[0] = make_float4(col[n][0], col[n][1], col[n][2], col[n][3]);
        *(float4*)&dst[4] = make_float4(col[n][4], col[n][5], col[n][6], col[n][7]);
    }
}

// ---------------------------------------------------------------------------
// Kernel 2: fused softmax stats + exact top-1024 per expert
// ---------------------------------------------------------------------------
__global__ __launch_bounds__(1024) void topk_kernel(
    float* __restrict__ out_vals, float* __restrict__ out_idx)
{
    extern __shared__ unsigned char smraw[];
    uint32_t* keys = reinterpret_cast<uint32_t*>(smraw);
    u64* cand = reinterpret_cast<u64*>(smraw + (size_t)T_TOK * 4);

    __shared__ uint32_t hist[256];
    __shared__ float red[1024];
    __shared__ uint32_t s_prefix, s_K, s_cnt, s_kmax;

    const int e = blockIdx.x;
    const int tid = threadIdx.x;
    const float* col = g_logits_t + (size_t)e * T_TOK;

    if (tid == 0) { s_prefix = 0u; s_K = SELK; s_cnt = 0u; s_kmax = 0u; }
    __syncthreads();

    uint32_t kmax = 0u;
    for (int ii = tid; ii < T_TOK / 4; ii += 1024) {
        float4 v = *(const float4*)&col[ii * 4];
        uint32_t u0 = __float_as_uint(v.x), u1 = __float_as_uint(v.y);
        uint32_t u2 = __float_as_uint(v.z), u3 = __float_as_uint(v.w);
        uint32_t k0 = (u0 & 0x80000000u) ? ~u0 : (u0 | 0x80000000u);
        uint32_t k1 = (u1 & 0x80000000u) ? ~u1 : (u1 | 0x80000000u);
        uint32_t k2 = (u2 & 0x80000000u) ? ~u2 : (u2 | 0x80000000u);
        uint32_t k3 = (u3 & 0x80000000u) ? ~u3 : (u3 | 0x80000000u);
        keys[ii * 4 + 0] = k0; keys[ii * 4 + 1] = k1;
        keys[ii * 4 + 2] = k2; keys[ii * 4 + 3] = k3;
        kmax = max(kmax, max(max(k0, k1), max(k2, k3)));
    }
#pragma unroll
    for (int off = 16; off > 0; off >>= 1)
        kmax = max(kmax, __shfl_xor_sync(0xFFFFFFFFu, kmax, off));
    if ((tid & 31) == 0) atomicMax(&s_kmax, kmax);
    __syncthreads();

    const uint32_t km = s_kmax;
    const float mx = __uint_as_float((km & 0x80000000u) ? (km ^ 0x80000000u) : ~km);

    // exp-sum from smem keys (no second gmem pass)
    float acc = 0.0f;
    for (int i = tid; i < T_TOK; i += 1024) {
        uint32_t k = keys[i];
        uint32_t u = (k & 0x80000000u) ? (k ^ 0x80000000u) : ~k;
        acc += EXPF(__uint_as_float(u) - mx);
    }
    red[tid] = acc;
    __syncthreads();
    for (int s = 512; s > 0; s >>= 1) {
        if (tid < s) red[tid] += red[tid + s];
        __syncthreads();
    }
    const float sum = red[0];
    if (tid == 0) { g_max[e] = mx; g_sum[e] = sum; }
    __syncthreads();

#pragma unroll
    for (int pass = 0; pass < 4; pass++) {
        const int shift = 24 - 8 * pass;
        const uint32_t maskhi = (pass == 0) ? 0u : (0xFFFFFFFFu << (shift + 8));
        if (tid < 256) hist[tid] = 0u;
        __syncthreads();
        const uint32_t pfx = s_prefix;
        for (int i = tid; i < T_TOK; i += 1024) {
            uint32_t key = keys[i];
            if ((key & maskhi) == pfx)
                atomicAdd(&hist[(key >> shift) & 0xFFu], 1u);
        }
        __syncthreads();
        if (tid == 0) {
            uint32_t cum = 0;
            for (int bin = 255; bin >= 0; bin--) {
                uint32_t c = hist[bin];
                if (cum + c >= s_K) {
                    s_K -= cum;
                    s_prefix |= ((uint32_t)bin) << shift;
                    break;
                }
                cum += c;
            }
        }
        __syncthreads();
    }
    const uint32_t V = s_prefix;

    for (int i = tid; i < T_TOK; i += 1024) {
        uint32_t key = keys[i];
        if (key >= V) {
            uint32_t u = (key & 0x80000000u) ? (key ^ 0x80000000u) : ~key;
            float p = __fdiv_rn(EXPF(__uint_as_float(u) - mx), sum);
            uint32_t pos = atomicAdd(&s_cnt, 1u);
            if (pos < CAND)
                cand[pos] = ((u64)__float_as_uint(p) << 32) |
                            (uint32_t)(~((uint32_t)i));
        }
    }
    __syncthreads();
    uint32_t n = s_cnt < CAND ? s_cnt : CAND;
    for (int i = tid; i < CAND; i += 1024)
        if ((uint32_t)i >= n) cand[i] = 0ull;
    __syncthreads();

    for (int ksz = 2; ksz <= CAND; ksz <<= 1) {
        for (int j = ksz >> 1; j > 0; j >>= 1) {
            for (int i = tid; i < CAND; i += 1024) {
                int ixj = i ^ j;
                if (ixj > i) {
                    u64 a = cand[i];
                    u64 c = cand[ixj];
                    bool up = ((i & ksz) == 0);
                    if ((a < c) == up) { cand[i] = c; cand[ixj] = a; }
                }
            }
            __syncthreads();
        }
    }

    {
        u64 c = cand[tid];
        out_vals[(size_t)e * CAP + tid] = __uint_as_float((uint32_t)(c >> 32));
        out_idx [(size_t)e * CAP + tid] = (float)(~((uint32_t)(c & 0xFFFFFFFFull)));
    }
}

// ---------------------------------------------------------------------------
// Kernel 3: probs, float4 vectorized
// ---------------------------------------------------------------------------
__global__ __launch_bounds__(256) void probs_kernel(
    const float* __restrict__ logits, float* __restrict__ probs)
{
    const int i4 = (blockIdx.x * 256 + threadIdx.x) * 4;
    const int e0 = i4 & (N_EXP - 1);
    float4 v = *(const float4*)&logits[i4];
    float4 r;
    r.x = __fdiv_rn(EXPF(v.x - g_max[e0 + 0]), g_sum[e0 + 0]);
    r.y = __fdiv_rn(EXPF(v.y - g_max[e0 + 1]), g_sum[e0 + 1]);
    r.z = __fdiv_rn(EXPF(v.z - g_max[e0 + 2]), g_sum[e0 + 2]);
    r.w = __fdiv_rn(EXPF(v.w - g_max[e0 + 3]), g_sum[e0 + 3]);
    *(float4*)&probs[i4] = r;
}

// ---------------------------------------------------------------------------
extern "C" void kernel_launch(void* const* d_in, const int* in_sizes, int n_in,
                              void* d_out, int out_size)
{
    const float* x = (const float*)d_in[0];
    const float* W = (const float*)d_in[1];
    const float* b = (const float*)d_in[2];

    float* out    = (float*)d_out;
    float* logits = out;
    float* probs  = out + (size_t)T_TOK * N_EXP;
    float* evals  = out + 2 * (size_t)T_TOK * N_EXP;
    float* eidx   = evals + (size_t)N_EXP * CAP;

    size_t topk_smem = (size_t)T_TOK * 4 + (size_t)CAND * 8;
    cudaFuncSetAttribute(topk_kernel,
                         cudaFuncAttributeMaxDynamicSharedMemorySize,
                         (int)topk_smem);

    gemm_kernel<<<T_TOK / BM, 128>>>(x, W, b, logits);
    topk_kernel<<<N_EXP, 1024, topk_smem>>>(evals, eidx);
    probs_kernel<<<(T_TOK * N_EXP) / (256 * 4), 256>>>(logits, probs);
}

// round 7
// speedup vs baseline: 1.0773x; 1.0773x over previous
#include <cuda_runtime.h>
#include <math.h>
#include <stdint.h>

#define T_TOK 32768
#define D_MOD 1024
#define N_EXP 64
#define CAP   1024
#define SELK  1032
#define CAND  2048

typedef unsigned long long u64;

extern "C" __device__ float __nv_expf(float);
#define EXPF(v) __nv_expf(v)

// Scratch
__device__ float g_logits_t[N_EXP * T_TOK];
__device__ float g_max[N_EXP];
__device__ float g_sum[N_EXP];

// ---------------- f32x2 helpers ----------------
__device__ __forceinline__ u64 pack_dup(float v) {
    u64 d; asm("mov.b64 %0, {%1, %1};" : "=l"(d) : "f"(v)); return d;
}
__device__ __forceinline__ u64 pack2(float lo, float hi) {
    u64 d; asm("mov.b64 %0, {%1, %2};" : "=l"(d) : "f"(lo), "f"(hi)); return d;
}
__device__ __forceinline__ void fma2(u64& d, u64 a, u64 b) {
    asm("fma.rn.f32x2 %0, %1, %2, %0;" : "+l"(d) : "l"(a), "l"(b));
}
__device__ __forceinline__ u64 add2(u64 a, u64 b) {
    u64 d; asm("add.rn.f32x2 %0, %1, %2;" : "=l"(d) : "l"(a), "l"(b)); return d;
}
__device__ __forceinline__ void unpack2(u64 v, float& lo, float& hi) {
    asm("mov.b64 {%0, %1}, %2;" : "=f"(lo), "=f"(hi) : "l"(v));
}
__device__ __forceinline__ void lds_v2u64(uint32_t addr, u64& a, u64& b) {
    asm volatile("ld.shared.v2.u64 {%0, %1}, [%2];"
                 : "=l"(a), "=l"(b) : "r"(addr));
}
__device__ __forceinline__ void lds_f4(uint32_t addr, float4& v) {
    asm volatile("ld.shared.v4.f32 {%0, %1, %2, %3}, [%4];"
                 : "=f"(v.x), "=f"(v.y), "=f"(v.z), "=f"(v.w) : "r"(addr));
}

// ---------------------------------------------------------------------------
// Kernel 1: SGEMM logits = x @ W + b, split-K2 bit-exact, FFMA2.
// 256 threads. Block tile 128m x 64n. Warp w -> experts 8w..8w+7 (B loads are
// warp-uniform broadcasts). Lane -> 4 m-rows. Thread tile 4m x 8n
// (accs packed along n). A tile XOR-swizzled: rows 512B, 4 clean wavefronts.
// ---------------------------------------------------------------------------
#define BM 128
#define KT 16

// f32 index of A element (kk, m) in swizzled tile
#define A_IDX(kk, m) (((kk) << 7) + ((m) ^ (((kk) & 7) << 2)))

__global__ __launch_bounds__(256, 2) void gemm_kernel(
    const float* __restrict__ x, const float* __restrict__ W,
    const float* __restrict__ bias, float* __restrict__ logits)
{
    __shared__ __align__(16) float As[KT * BM];    // swizzled [kk][m]
    __shared__ __align__(16) float Bs[KT][N_EXP];  // [kk][n]

    const int tid  = threadIdx.x;
    const int warp = tid >> 5;   // 0..7 -> expert group
    const int lane = tid & 31;   // -> 4 m rows
    const int m0   = blockIdx.x * BM;

    // staging maps
    const int am  = tid >> 2;    // 0..63 (+64 second pass)
    const int akg = tid & 3;     // k-group of 4
    const int wkk = tid >> 4;    // 0..15
    const int wng = tid & 15;    // n-group of 4

    u64 acc[2][4][4];            // [half][m][n-pair]
#pragma unroll
    for (int h = 0; h < 2; h++)
#pragma unroll
        for (int m = 0; m < 4; m++)
#pragma unroll
            for (int np = 0; np < 4; np++) acc[h][m][np] = 0ull;

    const uint32_t aBase = (uint32_t)__cvta_generic_to_shared(&As[0]);
    const uint32_t bBase = (uint32_t)__cvta_generic_to_shared(&Bs[0][0]);
    const uint32_t bRow  = bBase + (uint32_t)(warp * 8) * 4u;

    // prefetch tile 0
    float4 xa0 = *(const float4*)&x[(size_t)(m0 + am) * D_MOD + akg * 4];
    float4 xa1 = *(const float4*)&x[(size_t)(m0 + am + 64) * D_MOD + akg * 4];
    float4 wv  = *(const float4*)&W[(size_t)wkk * N_EXP + wng * 4];

    for (int t = 0; t < D_MOD / KT; t++) {
#pragma unroll
        for (int i = 0; i < 4; i++) {
            As[A_IDX(akg * 4 + i, am)]      = (&xa0.x)[i];
            As[A_IDX(akg * 4 + i, am + 64)] = (&xa1.x)[i];
        }
        *(float4*)&Bs[wkk][wng * 4] = wv;
        __syncthreads();

        if (t < D_MOD / KT - 1) {
            const int k0 = (t + 1) * KT;
            xa0 = *(const float4*)&x[(size_t)(m0 + am) * D_MOD + k0 + akg * 4];
            xa1 = *(const float4*)&x[(size_t)(m0 + am + 64) * D_MOD + k0 + akg * 4];
            wv  = *(const float4*)&W[(size_t)(k0 + wkk) * N_EXP + wng * 4];
        }

        const int h = (t < 32) ? 0 : 1;
        if (h == 0) {
#pragma unroll
            for (int kk = 0; kk < KT; kk++) {
                float4 a;
                lds_f4(aBase + (uint32_t)A_IDX(kk, lane * 4) * 4u, a);
                u64 b0, b1, b2, b3;
                uint32_t br = bRow + (uint32_t)(kk * N_EXP) * 4u;
                lds_v2u64(br,      b0, b1);
                lds_v2u64(br + 16, b2, b3);
                u64 a0 = pack_dup(a.x), a1 = pack_dup(a.y);
                u64 a2 = pack_dup(a.z), a3 = pack_dup(a.w);
                fma2(acc[0][0][0], a0, b0); fma2(acc[0][0][1], a0, b1);
                fma2(acc[0][0][2], a0, b2); fma2(acc[0][0][3], a0, b3);
                fma2(acc[0][1][0], a1, b0); fma2(acc[0][1][1], a1, b1);
                fma2(acc[0][1][2], a1, b2); fma2(acc[0][1][3], a1, b3);
                fma2(acc[0][2][0], a2, b0); fma2(acc[0][2][1], a2, b1);
                fma2(acc[0][2][2], a2, b2); fma2(acc[0][2][3], a2, b3);
                fma2(acc[0][3][0], a3, b0); fma2(acc[0][3][1], a3, b1);
                fma2(acc[0][3][2], a3, b2); fma2(acc[0][3][3], a3, b3);
            }
        } else {
#pragma unroll
            for (int kk = 0; kk < KT; kk++) {
                float4 a;
                lds_f4(aBase + (uint32_t)A_IDX(kk, lane * 4) * 4u, a);
                u64 b0, b1, b2, b3;
                uint32_t br = bRow + (uint32_t)(kk * N_EXP) * 4u;
                lds_v2u64(br,      b0, b1);
                lds_v2u64(br + 16, b2, b3);
                u64 a0 = pack_dup(a.x), a1 = pack_dup(a.y);
                u64 a2 = pack_dup(a.z), a3 = pack_dup(a.w);
                fma2(acc[1][0][0], a0, b0); fma2(acc[1][0][1], a0, b1);
                fma2(acc[1][0][2], a0, b2); fma2(acc[1][0][3], a0, b3);
                fma2(acc[1][1][0], a1, b0); fma2(acc[1][1][1], a1, b1);
                fma2(acc[1][1][2], a1, b2); fma2(acc[1][1][3], a1, b3);
                fma2(acc[1][2][0], a2, b0); fma2(acc[1][2][1], a2, b1);
                fma2(acc[1][2][2], a2, b2); fma2(acc[1][2][3], a2, b3);
                fma2(acc[1][3][0], a3, b0); fma2(acc[1][3][1], a3, b1);
                fma2(acc[1][3][2], a3, b2); fma2(acc[1][3][3], a3, b3);
            }
        }
        __syncthreads();
    }

    // epilogue: (acc0 + acc1) + bias, componentwise RN (bit-exact split-K2)
    u64 bp[4];
#pragma unroll
    for (int np = 0; np < 4; np++)
        bp[np] = pack2(bias[warp * 8 + 2 * np], bias[warp * 8 + 2 * np + 1]);

    float col[8][4];   // [n][m]
#pragma unroll
    for (int m = 0; m < 4; m++) {
        float r[8];
#pragma unroll
        for (int np = 0; np < 4; np++) {
            u64 s = add2(add2(acc[0][m][np], acc[1][m][np]), bp[np]);
            unpack2(s, r[2 * np], r[2 * np + 1]);
#pragma unroll
            for (int q = 0; q < 2; q++) col[2 * np + q][m] = r[2 * np + q];
        }
        const int gm = m0 + lane * 4 + m;
        *(float4*)&logits[(size_t)gm * N_EXP + warp * 8] =
            make_float4(r[0], r[1], r[2], r[3]);
        *(float4*)&logits[(size_t)gm * N_EXP + warp * 8 + 4] =
            make_float4(r[4], r[5], r[6], r[7]);
    }
#pragma unroll
    for (int n = 0; n < 8; n++) {
        float* dst = &g_logits_t[(size_t)(warp * 8 + n) * T_TOK + m0 + lane * 4];
        *(float4*)dst = make_float4(col[n][0], col[n][1], col[n][2], col[n][3]);
    }
}

// ---------------------------------------------------------------------------
// Kernel 2: fused softmax stats + exact top-1024 per expert
// ---------------------------------------------------------------------------
__global__ __launch_bounds__(1024) void topk_kernel(
    float* __restrict__ out_vals, float* __restrict__ out_idx)
{
    extern __shared__ unsigned char smraw[];
    uint32_t* keys = reinterpret_cast<uint32_t*>(smraw);
    u64* cand = reinterpret_cast<u64*>(smraw + (size_t)T_TOK * 4);

    __shared__ uint32_t hist[256];
    __shared__ float red[1024];
    __shared__ uint32_t s_prefix, s_K, s_cnt, s_kmax;

    const int e = blockIdx.x;
    const int tid = threadIdx.x;
    const float* col = g_logits_t + (size_t)e * T_TOK;

    if (tid == 0) { s_prefix = 0u; s_K = SELK; s_cnt = 0u; s_kmax = 0u; }
    __syncthreads();

    uint32_t kmax = 0u;
    for (int ii = tid; ii < T_TOK / 4; ii += 1024) {
        float4 v = *(const float4*)&col[ii * 4];
        uint32_t u0 = __float_as_uint(v.x), u1 = __float_as_uint(v.y);
        uint32_t u2 = __float_as_uint(v.z), u3 = __float_as_uint(v.w);
        uint32_t k0 = (u0 & 0x80000000u) ? ~u0 : (u0 | 0x80000000u);
        uint32_t k1 = (u1 & 0x80000000u) ? ~u1 : (u1 | 0x80000000u);
        uint32_t k2 = (u2 & 0x80000000u) ? ~u2 : (u2 | 0x80000000u);
        uint32_t k3 = (u3 & 0x80000000u) ? ~u3 : (u3 | 0x80000000u);
        keys[ii * 4 + 0] = k0; keys[ii * 4 + 1] = k1;
        keys[ii * 4 + 2] = k2; keys[ii * 4 + 3] = k3;
        kmax = max(kmax, max(max(k0, k1), max(k2, k3)));
    }
#pragma unroll
    for (int off = 16; off > 0; off >>= 1)
        kmax = max(kmax, __shfl_xor_sync(0xFFFFFFFFu, kmax, off));
    if ((tid & 31) == 0) atomicMax(&s_kmax, kmax);
    __syncthreads();

    const uint32_t km = s_kmax;
    const float mx = __uint_as_float((km & 0x80000000u) ? (km ^ 0x80000000u) : ~km);

    float acc = 0.0f;
    for (int i = tid; i < T_TOK; i += 1024) {
        uint32_t k = keys[i];
        uint32_t u = (k & 0x80000000u) ? (k ^ 0x80000000u) : ~k;
        acc += EXPF(__uint_as_float(u) - mx);
    }
    red[tid] = acc;
    __syncthreads();
    for (int s = 512; s > 0; s >>= 1) {
        if (tid < s) red[tid] += red[tid + s];
        __syncthreads();
    }
    const float sum = red[0];
    if (tid == 0) { g_max[e] = mx; g_sum[e] = sum; }
    __syncthreads();

#pragma unroll
    for (int pass = 0; pass < 4; pass++) {
        const int shift = 24 - 8 * pass;
        const uint32_t maskhi = (pass == 0) ? 0u : (0xFFFFFFFFu << (shift + 8));
        if (tid < 256) hist[tid] = 0u;
        __syncthreads();
        const uint32_t pfx = s_prefix;
        for (int i = tid; i < T_TOK; i += 1024) {
            uint32_t key = keys[i];
            if ((key & maskhi) == pfx)
                atomicAdd(&hist[(key >> shift) & 0xFFu], 1u);
        }
        __syncthreads();
        if (tid == 0) {
            uint32_t cum = 0;
            for (int bin = 255; bin >= 0; bin--) {
                uint32_t c = hist[bin];
                if (cum + c >= s_K) {
                    s_K -= cum;
                    s_prefix |= ((uint32_t)bin) << shift;
                    break;
                }
                cum += c;
            }
        }
        __syncthreads();
    }
    const uint32_t V = s_prefix;

    for (int i = tid; i < T_TOK; i += 1024) {
        uint32_t key = keys[i];
        if (key >= V) {
            uint32_t u = (key & 0x80000000u) ? (key ^ 0x80000000u) : ~key;
            float p = __fdiv_rn(EXPF(__uint_as_float(u) - mx), sum);
            uint32_t pos = atomicAdd(&s_cnt, 1u);
            if (pos < CAND)
                cand[pos] = ((u64)__float_as_uint(p) << 32) |
                            (uint32_t)(~((uint32_t)i));
        }
    }
    __syncthreads();
    uint32_t n = s_cnt < CAND ? s_cnt : CAND;
    for (int i = tid; i < CAND; i += 1024)
        if ((uint32_t)i >= n) cand[i] = 0ull;
    __syncthreads();

    for (int ksz = 2; ksz <= CAND; ksz <<= 1) {
        for (int j = ksz >> 1; j > 0; j >>= 1) {
            for (int i = tid; i < CAND; i += 1024) {
                int ixj = i ^ j;
                if (ixj > i) {
                    u64 a = cand[i];
                    u64 c = cand[ixj];
                    bool up = ((i & ksz) == 0);
                    if ((a < c) == up) { cand[i] = c; cand[ixj] = a; }
                }
            }
            __syncthreads();
        }
    }

    {
        u64 c = cand[tid];
        out_vals[(size_t)e * CAP + tid] = __uint_as_float((uint32_t)(c >> 32));
        out_idx [(size_t)e * CAP + tid] = (float)(~((uint32_t)(c & 0xFFFFFFFFull)));
    }
}

// ---------------------------------------------------------------------------
// Kernel 3: probs, float4 vectorized
// ---------------------------------------------------------------------------
__global__ __launch_bounds__(256) void probs_kernel(
    const float* __restrict__ logits, float* __restrict__ probs)
{
    const int i4 = (blockIdx.x * 256 + threadIdx.x) * 4;
    const int e0 = i4 & (N_EXP - 1);
    float4 v = *(const float4*)&logits[i4];
    float4 r;
    r.x = __fdiv_rn(EXPF(v.x - g_max[e0 + 0]), g_sum[e0 + 0]);
    r.y = __fdiv_rn(EXPF(v.y - g_max[e0 + 1]), g_sum[e0 + 1]);
    r.z = __fdiv_rn(EXPF(v.z - g_max[e0 + 2]), g_sum[e0 + 2]);
    r.w = __fdiv_rn(EXPF(v.w - g_max[e0 + 3]), g_sum[e0 + 3]);
    *(float4*)&probs[i4] = r;
}

// ---------------------------------------------------------------------------
extern "C" void kernel_launch(void* const* d_in, const int* in_sizes, int n_in,
                              void* d_out, int out_size)
{
    const float* x = (const float*)d_in[0];
    const float* W = (const float*)d_in[1];
    const float* b = (const float*)d_in[2];

    float* out    = (float*)d_out;
    float* logits = out;
    float* probs  = out + (size_t)T_TOK * N_EXP;
    float* evals  = out + 2 * (size_t)T_TOK * N_EXP;
    float* eidx   = evals + (size_t)N_EXP * CAP;

    size_t topk_smem = (size_t)T_TOK * 4 + (size_t)CAND * 8;
    cudaFuncSetAttribute(topk_kernel,
                         cudaFuncAttributeMaxDynamicSharedMemorySize,
                         (int)topk_smem);

    gemm_kernel<<<T_TOK / BM, 256>>>(x, W, b, logits);
    topk_kernel<<<N_EXP, 1024, topk_smem>>>(evals, eidx);
    probs_kernel<<<(T_TOK * N_EXP) / (256 * 4), 256>>>(logits, probs);
}